// round 13
// baseline (speedup 1.0000x reference)
#include <cuda_runtime.h>
#include <math.h>

#define NMID 500000
#define DD 64
#define KI 4
#define CC 512
#define SS 256
#define BB 512
#define NEGV (-4294967295.0f)
#define FMIN2 (-3.402823466e38f)

#define IST 68
#define QST 264
#define SST 260
#define SM_FLOATS 51328

typedef unsigned long long u64;

__device__ __forceinline__ u64 splat2(float x) {
    u64 r; asm("mov.b64 %0, {%1,%1};" : "=l"(r) : "f"(x)); return r;
}
__device__ __forceinline__ void ffma2(u64& acc, u64 a, u64 b) {
    asm("fma.rn.f32x2 %0, %1, %2, %0;" : "+l"(acc) : "l"(a), "l"(b));
}
__device__ __forceinline__ float2 unpack2(u64 v) {
    float2 f; asm("mov.b64 {%0,%1}, %2;" : "=f"(f.x), "=f"(f.y) : "l"(v)); return f;
}
__device__ __forceinline__ float tanh_fast(float x) {
    float t = __expf(2.f * x);
    return 1.f - __fdividef(2.f, t + 1.f);
}

__device__ float g_wmean[KI*DD];
__device__ float g_posSum[DD];
__device__ float g_cand0[CC*DD];
__device__ float g_cand[CC*DD];
__device__ float g_candW4[CC*DD];
__device__ float g_transT[(size_t)CC*CC];
__device__ float g_seq[(size_t)BB*SS*DD];
__device__ float g_mean[BB*DD];

// ---------------- K0 ----------------
__global__ void k_pre(const float* __restrict__ pos) {
    int t = threadIdx.x;
    if (t < KI*DD) g_wmean[t] = 0.f;
    if (t < DD) {
        float s = 0.f;
        for (int i = 0; i < SS; i++) s += pos[i*DD + t];
        g_posSum[t] = s;
    }
}

// ---------------- K1 ----------------
__global__ void k_wmean(const float* __restrict__ E, const float* __restrict__ W2) {
    __shared__ float red[8*256];
    int t = threadIdx.x, l = t & 31, wi = t >> 5;
    int gw = (blockIdx.x*blockDim.x + t) >> 5;
    int TW = (gridDim.x*blockDim.x) >> 5;
    float2 w2[KI];
#pragma unroll
    for (int k = 0; k < KI; k++) {
        w2[k].x = W2[k*DD + 2*l];
        w2[k].y = W2[k*DD + 2*l + 1];
    }
    float2 acc[KI];
#pragma unroll
    for (int k = 0; k < KI; k++) acc[k] = make_float2(0.f, 0.f);
    const float2* E2 = (const float2*)E;
    for (long n = gw; n < NMID; n += TW) {
        float2 e = E2[n*32 + l];
#pragma unroll
        for (int k = 0; k < KI; k++) {
            float p = fmaf(e.x, w2[k].x, e.y*w2[k].y);
#pragma unroll
            for (int o = 16; o; o >>= 1) p += __shfl_xor_sync(~0u, p, o);
            acc[k].x = fmaf(p, e.x, acc[k].x);
            acc[k].y = fmaf(p, e.y, acc[k].y);
        }
    }
#pragma unroll
    for (int k = 0; k < KI; k++) {
        red[wi*256 + k*64 + 2*l]     = acc[k].x;
        red[wi*256 + k*64 + 2*l + 1] = acc[k].y;
    }
    __syncthreads();
    if (t < 256) {
        float s = 0.f;
#pragma unroll
        for (int w = 0; w < 8; w++) s += red[w*256 + t];
        atomicAdd(&g_wmean[t], s);
    }
}

// ---------------- K2 ----------------
__global__ void k_cand(const float* __restrict__ W3, const float* __restrict__ W1,
                       const float* __restrict__ W4) {
    __shared__ float row[DD];
    int d = threadIdx.x, c = blockIdx.x;
    float v = 0.f;
#pragma unroll
    for (int k = 0; k < KI; k++) v = fmaf(W3[k*CC + c], g_wmean[k*DD + d], v);
    row[d] = v;
    g_cand0[c*DD + d] = v;
    __syncthreads();
    float a = 0.f, bv = 0.f;
#pragma unroll 8
    for (int e = 0; e < DD; e++) {
        float r = row[e];
        a  = fmaf(r, W1[e*DD + d], a);
        bv = fmaf(r, W4[e*DD + d], bv);
    }
    g_cand[c*DD + d]   = tanhf(a);
    g_candW4[c*DD + d] = bv;
}

// ---------------- K3: exact (expf, scalar float4 dots) ----------------
__global__ void k_trans() {
    __shared__ float c0j[DD];
    __shared__ float red[8];
    __shared__ float bmax, bsum;
    int t = threadIdx.x, j = blockIdx.x, w = t >> 5, l = t & 31;
    if (t < DD) c0j[t] = g_cand0[j*DD + t];
    __syncthreads();
    float v0 = 0.f, v1 = 0.f;
    {
        const float4* r4 = (const float4*)(g_candW4 + (size_t)t*DD);
#pragma unroll
        for (int e4 = 0; e4 < 16; e4++) {
            float4 q = r4[e4];
            v0 = fmaf(q.x, c0j[4*e4], v0);   v0 = fmaf(q.y, c0j[4*e4+1], v0);
            v0 = fmaf(q.z, c0j[4*e4+2], v0); v0 = fmaf(q.w, c0j[4*e4+3], v0);
        }
        r4 = (const float4*)(g_candW4 + (size_t)(t+256)*DD);
#pragma unroll
        for (int e4 = 0; e4 < 16; e4++) {
            float4 q = r4[e4];
            v1 = fmaf(q.x, c0j[4*e4], v1);   v1 = fmaf(q.y, c0j[4*e4+1], v1);
            v1 = fmaf(q.z, c0j[4*e4+2], v1); v1 = fmaf(q.w, c0j[4*e4+3], v1);
        }
    }
    float m = fmaxf(v0, v1);
#pragma unroll
    for (int o = 16; o; o >>= 1) m = fmaxf(m, __shfl_xor_sync(~0u, m, o));
    if (l == 0) red[w] = m;
    __syncthreads();
    if (t == 0) { float mm = red[0]; for (int i = 1; i < 8; i++) mm = fmaxf(mm, red[i]); bmax = mm; }
    __syncthreads();
    float p0 = expf(v0 - bmax), p1 = expf(v1 - bmax);
    float s = p0 + p1;
#pragma unroll
    for (int o = 16; o; o >>= 1) s += __shfl_xor_sync(~0u, s, o);
    if (l == 0) red[w] = s;
    __syncthreads();
    if (t == 0) { float ss = 0.f; for (int i = 0; i < 8; i++) ss += red[i]; bsum = ss; }
    __syncthreads();
    float inv = 1.f / bsum;
    g_transT[(size_t)j*CC + t]       = p0 * inv;
    g_transT[(size_t)j*CC + t + 256] = p1 * inv;
}

// ---------------- K4a: heavy per-batch part (1024 threads) ----------------
__global__ void __launch_bounds__(1024,1) k_heavy(
    const float* __restrict__ E, const float* __restrict__ pos,
    const float* __restrict__ dw, const float* __restrict__ db,
    const int* __restrict__ his, const int* __restrict__ mask)
{
    extern __shared__ float sm[];
    float* itemsS = sm;
    float* qT     = sm + 17408;
    float* sc     = sm + 34304;
    float* maskS  = sm + 50944;
    float* colS   = sm + 51200;
    __shared__ float sDen;

    int b = blockIdx.x, t = threadIdx.x, w = t >> 5, l = t & 31;

    // ---- A: loads ----
    if (t < SS) maskS[t] = (float)mask[b*SS + t];
    if (t < 64) colS[t] = 0.f;
    {
        float* dwS = sc; float* biasS = sc + 4096;
        for (int i = t; i < 4096; i += 1024) dwS[i] = dw[i];
        if (t < 64) biasS[t] = db[t];
    }
    {
        const float4* E4 = (const float4*)E;
        float4* it4 = (float4*)itemsS;
        const int* hr = his + b*SS;
        for (int f = t; f < SS*16; f += 1024) {
            int s = f >> 4, c = f & 15;
            it4[s*17 + c] = E4[(size_t)hr[s]*16 + c];
        }
    }
    __syncthreads();
    if (w == 0) {
        float s = 0.f;
        for (int i = l; i < SS; i += 32) s += maskS[i];
#pragma unroll
        for (int o = 16; o; o >>= 1) s += __shfl_xor_sync(~0u, s, o);
        if (l == 0) sDen = 1.f / (s + 1e-9f);
    }

    // ---- B: qT = tanh((items+pos)@dense_w + b); thread = 1 row x 16 d ----
    {
        float* dwS = sc; float* biasS = sc + 4096;
        int s = t >> 2, q4 = t & 3;
        int d0 = 16*q4;
        u64 acc[8];
#pragma unroll
        for (int i = 0; i < 8; i++) acc[i] = 0ull;
#pragma unroll 4
        for (int e = 0; e < 64; e++) {
            float xe = itemsS[s*IST + e] + pos[s*DD + e];
            u64 xs = splat2(xe);
            const ulonglong2* wp = (const ulonglong2*)&dwS[e*64 + d0];
#pragma unroll
            for (int q = 0; q < 4; q++) {
                ulonglong2 wv = wp[q];
                ffma2(acc[2*q],   xs, wv.x);
                ffma2(acc[2*q+1], xs, wv.y);
            }
        }
#pragma unroll
        for (int i = 0; i < 8; i++) {
            float2 p = unpack2(acc[i]);
            int d = d0 + 2*i;
            qT[d*QST + s]     = tanhf(p.x + biasS[d]);
            qT[(d+1)*QST + s] = tanhf(p.y + biasS[d+1]);
        }
    }
    __syncthreads();

    // ---- C: scores -> softmax -> seq (4 groups of 64 query rows) ----
    float rs0 = 0.f, rs1 = 0.f;
    for (int g = 0; g < 4; g++) {
        int s0 = g*64;
        // C1: thread = 8 rows x 2 cols
        {
            int ty = t >> 7;       // 0..7 -> rows 8*ty
            int tx = t & 127;      // cols 2*tx
            u64 acc[4][2];
#pragma unroll
            for (int i = 0; i < 4; i++) { acc[i][0] = 0ull; acc[i][1] = 0ull; }
#pragma unroll 4
            for (int e = 0; e < 64; e++) {
                const float* qe = &qT[e*QST];
                ulonglong2 a01 = *(const ulonglong2*)&qe[s0 + 8*ty];
                ulonglong2 a23 = *(const ulonglong2*)&qe[s0 + 8*ty + 4];
                float2 bf = *(const float2*)&qe[2*tx];
                u64 b0 = splat2(bf.x), b1 = splat2(bf.y);
                ffma2(acc[0][0], a01.x, b0); ffma2(acc[0][1], a01.x, b1);
                ffma2(acc[1][0], a01.y, b0); ffma2(acc[1][1], a01.y, b1);
                ffma2(acc[2][0], a23.x, b0); ffma2(acc[2][1], a23.x, b1);
                ffma2(acc[3][0], a23.y, b0); ffma2(acc[3][1], a23.y, b1);
            }
#pragma unroll
            for (int rp = 0; rp < 4; rp++) {
                float2 c0 = unpack2(acc[rp][0]);  // col 2tx,   rows (2rp,2rp+1)
                float2 c1 = unpack2(acc[rp][1]);  // col 2tx+1
                *(float2*)&sc[(8*ty + 2*rp)*SST + 2*tx]     = make_float2(c0.x, c1.x);
                *(float2*)&sc[(8*ty + 2*rp + 1)*SST + 2*tx] = make_float2(c0.y, c1.y);
            }
        }
        __syncthreads();
        // C2: masked row softmax (32 warps, 2 rows each) — exact expf
        for (int rr = w; rr < 64; rr += 32) {
            int s = s0 + rr;
            if (maskS[s] == 0.f) {
                for (int c = l; c < 256; c += 32) sc[rr*SST + c] = 0.f;
            } else {
                float v[8]; float mx = FMIN2;
#pragma unroll
                for (int c = 0; c < 8; c++) {
                    float rawv = sc[rr*SST + l + 32*c] * 0.125f;
                    if (maskS[l + 32*c] == 0.f) rawv = NEGV;
                    v[c] = rawv; mx = fmaxf(mx, rawv);
                }
#pragma unroll
                for (int o = 16; o; o >>= 1) mx = fmaxf(mx, __shfl_xor_sync(~0u, mx, o));
                float sum = 0.f;
#pragma unroll
                for (int c = 0; c < 8; c++) { v[c] = expf(v[c] - mx); sum += v[c]; }
#pragma unroll
                for (int o = 16; o; o >>= 1) sum += __shfl_xor_sync(~0u, sum, o);
                float inv = 1.f / sum;
#pragma unroll
                for (int c = 0; c < 8; c++) sc[rr*SST + l + 32*c] = v[c]*inv;
            }
        }
        __syncthreads();
        // C3: seq tile [64x64]; thread = 2 rows x 2 cols (cols packed)
        {
            int ry = t >> 5;       // 0..31 -> rows 2*ry
            int rx = t & 31;       // cols 2*rx
            u64 acc0 = 0ull, acc1 = 0ull;
            const float* r0p = &sc[(2*ry)*SST];
            const float* r1p = &sc[(2*ry + 1)*SST];
#pragma unroll 4
            for (int k = 0; k < 256; k += 2) {
                float2 af0 = *(const float2*)&r0p[k];
                float2 af1 = *(const float2*)&r1p[k];
                u64 bk  = *(const u64*)&itemsS[k*IST + 2*rx];
                u64 bk1 = *(const u64*)&itemsS[(k+1)*IST + 2*rx];
                ffma2(acc0, splat2(af0.x), bk);
                ffma2(acc1, splat2(af1.x), bk);
                ffma2(acc0, splat2(af0.y), bk1);
                ffma2(acc1, splat2(af1.y), bk1);
            }
            float2 u0 = unpack2(acc0), u1 = unpack2(acc1);
            float* so = &g_seq[((size_t)b*SS + s0 + 2*ry)*DD + 2*rx];
            *(float2*)so = u0;
            *(float2*)(so + DD) = u1;
            rs0 += u0.x + u1.x;
            rs1 += u0.y + u1.y;
        }
        __syncthreads();
    }
    {
        int rx = t & 31;
        atomicAdd(&colS[2*rx],   rs0);
        atomicAdd(&colS[2*rx+1], rs1);
    }
    __syncthreads();
    if (t < 64) g_mean[b*64 + t] = (colS[t] + g_posSum[t]) * sDen;
}

// ---------------- K4b: tail per-batch part (512 threads) ----------------
__global__ void __launch_bounds__(512) k_tail(
    const float* __restrict__ E, const float* __restrict__ W1,
    const float* __restrict__ pos, const int* __restrict__ mask,
    const int* __restrict__ midb, float* __restrict__ out, long out_size)
{
    __shared__ float W1S[4096];
    __shared__ float logitsS[512];
    __shared__ float mhS[64];
    __shared__ float wrS[4*260];
    __shared__ float aqS[256];
    __shared__ float uebS[256];
    __shared__ float maskS[256];
    __shared__ float itemS[64];
    __shared__ float rv[16]; __shared__ int riS[16];
    __shared__ int idxS[4];
    __shared__ float dotS[4]; __shared__ int ridxS;

    int b = blockIdx.x, t = threadIdx.x, w = t >> 5, l = t & 31;

    if (t < SS) maskS[t] = (float)mask[b*SS + t];
    if (t < 64) itemS[t] = E[(size_t)midb[b]*DD + t];
    for (int i = t; i < 4096; i += 512) W1S[i] = W1[i];
    __syncthreads();

    // mean_h (accurate path: scalar fp32 + tanhf — matches round-12 bitwise)
    if (t < 64) {
        float a = 0.f;
        float mv = 0.f; // placeholder
#pragma unroll 16
        for (int e = 0; e < 64; e++) a = fmaf(g_mean[b*64 + e], W1S[e*64 + t], a);
        mhS[t] = tanhf(a);
        (void)mv;
    }
    __syncthreads();
    {
        const float4* cr = (const float4*)&g_cand[(size_t)t*64];
        float a = 0.f;
#pragma unroll
        for (int e4 = 0; e4 < 16; e4++) {
            float4 cv = cr[e4];
            a = fmaf(cv.x, mhS[4*e4], a);   a = fmaf(cv.y, mhS[4*e4+1], a);
            a = fmaf(cv.z, mhS[4*e4+2], a); a = fmaf(cv.w, mhS[4*e4+3], a);
        }
        logitsS[t] = a;
    }
    __syncthreads();
    float lgv;
    {
        const float4* tr = (const float4*)&g_transT[(size_t)t*CC];
        float a = 0.f;
#pragma unroll 8
        for (int i4 = 0; i4 < 128; i4++) {
            float4 tv = tr[i4];
            a = fmaf(tv.x, logitsS[4*i4], a);   a = fmaf(tv.y, logitsS[4*i4+1], a);
            a = fmaf(tv.z, logitsS[4*i4+2], a); a = fmaf(tv.w, logitsS[4*i4+3], a);
        }
        lgv = a;
    }
    __syncthreads();
    logitsS[t] = lgv;
    __syncthreads();
    for (int p = 0; p < 4; p++) {
        float bv = logitsS[t]; int bi = t;
#pragma unroll
        for (int o = 16; o; o >>= 1) {
            float ov = __shfl_xor_sync(~0u, bv, o);
            int   oi = __shfl_xor_sync(~0u, bi, o);
            if (ov > bv || (ov == bv && oi < bi)) { bv = ov; bi = oi; }
        }
        if (l == 0) { rv[w] = bv; riS[w] = bi; }
        __syncthreads();
        if (t == 0) {
            float B2 = rv[0]; int BI = riS[0];
            for (int i = 1; i < 16; i++)
                if (rv[i] > B2 || (rv[i] == B2 && riS[i] < BI)) { B2 = rv[i]; BI = riS[i]; }
            idxS[p] = BI; logitsS[BI] = FMIN2;
        }
        __syncthreads();
    }
    if (t < 256) { int k = t >> 6, d = t & 63; aqS[t] = g_cand[(size_t)idxS[k]*64 + d]; }
    __syncthreads();

    // D: multi-interest attention (fast math OK: feeds outputs 0/1 only)
    {
        int s = t >> 1, half = t & 1;
        int d0 = 32*half;
        u64 acc[16];
#pragma unroll
        for (int i = 0; i < 16; i++) acc[i] = 0ull;
        const float* sr = &g_seq[((size_t)b*SS + s)*DD];
#pragma unroll 4
        for (int e = 0; e < 64; e++) {
            float xe = sr[e] + pos[s*DD + e];
            u64 xs = splat2(xe);
            const ulonglong2* wp = (const ulonglong2*)&W1S[e*64 + d0];
#pragma unroll
            for (int q = 0; q < 8; q++) {
                ulonglong2 wv = wp[q];
                ffma2(acc[2*q],   xs, wv.x);
                ffma2(acc[2*q+1], xs, wv.y);
            }
        }
        float ihv[32];
#pragma unroll
        for (int i = 0; i < 16; i++) {
            float2 p = unpack2(acc[i]);
            ihv[2*i]   = tanh_fast(p.x);
            ihv[2*i+1] = tanh_fast(p.y);
        }
        float wv[4];
#pragma unroll
        for (int k = 0; k < 4; k++) {
            float a = 0.f;
            const float* aq = &aqS[k*64 + d0];
#pragma unroll
            for (int i = 0; i < 32; i++) a = fmaf(ihv[i], aq[i], a);
            a += __shfl_xor_sync(~0u, a, 1);
            wv[k] = a;
        }
        if (half == 0) {
            float m = maskS[s];
#pragma unroll
            for (int k = 0; k < 4; k++)
                wrS[k*260 + s] = (m == 0.f) ? NEGV : wv[k];
        }
    }
    __syncthreads();
    if (w < 4) {
        float v[8]; float mx = FMIN2;
#pragma unroll
        for (int c = 0; c < 8; c++) { v[c] = wrS[w*260 + l + 32*c]; mx = fmaxf(mx, v[c]); }
#pragma unroll
        for (int o = 16; o; o >>= 1) mx = fmaxf(mx, __shfl_xor_sync(~0u, mx, o));
        float sum = 0.f;
#pragma unroll
        for (int c = 0; c < 8; c++) { v[c] = __expf(v[c] - mx); sum += v[c]; }
#pragma unroll
        for (int o = 16; o; o >>= 1) sum += __shfl_xor_sync(~0u, sum, o);
        float inv = 1.f / sum;
#pragma unroll
        for (int c = 0; c < 8; c++) wrS[w*260 + l + 32*c] = v[c]*inv;
    }
    __syncthreads();
    if (t < 256) {
        int k = t >> 6, d = t & 63;
        const float* wp = &wrS[k*260];
        const float* sp = &g_seq[(size_t)b*SS*DD + d];
        float a = 0.f;
#pragma unroll 8
        for (int s = 0; s < 256; s++) a = fmaf(wp[s], sp[(size_t)s*64], a);
        uebS[t] = a;
        long off = 32768 + (long)b*256 + t;
        if (off < out_size) out[off] = a;
    }
    __syncthreads();
    if (w < 4) {
        float p = uebS[w*64 + l]*itemS[l] + uebS[w*64 + l + 32]*itemS[l + 32];
#pragma unroll
        for (int o = 16; o; o >>= 1) p += __shfl_xor_sync(~0u, p, o);
        if (l == 0) dotS[w] = p;
    }
    __syncthreads();
    if (t == 0) {
        float bv2 = dotS[0]; int bi2 = 0;
        for (int k = 1; k < 4; k++) if (dotS[k] > bv2) { bv2 = dotS[k]; bi2 = k; }
        ridxS = bi2;
    }
    __syncthreads();
    if (t < 64) {
        long off = (long)b*64 + t;
        if (off < out_size) out[off] = uebS[ridxS*64 + t];
    }
    if (t < 4) {
        long off = 163840 + (long)b*4 + t;
        if (off < out_size) out[off] = (float)idxS[t];
    }
}

extern "C" void kernel_launch(void* const* d_in, const int* in_sizes, int n_in,
                              void* d_out, int out_size) {
    const float* E    = (const float*)d_in[0];
    const float* W1   = (const float*)d_in[1];
    const float* W2   = (const float*)d_in[2];
    const float* W3   = (const float*)d_in[3];
    const float* W4   = (const float*)d_in[4];
    const float* pos  = (const float*)d_in[5];
    const float* dw   = (const float*)d_in[6];
    const float* db   = (const float*)d_in[7];
    const int*   his  = (const int*)d_in[8];
    const int*   mask = (const int*)d_in[9];
    const int*   midb = (const int*)d_in[10];
    float* out = (float*)d_out;

    cudaFuncSetAttribute(k_heavy, cudaFuncAttributeMaxDynamicSharedMemorySize,
                         SM_FLOATS * (int)sizeof(float));

    k_pre<<<1, 256>>>(pos);
    k_wmean<<<1184, 256>>>(E, W2);
    k_cand<<<CC, DD>>>(W3, W1, W4);
    k_heavy<<<BB, 1024, SM_FLOATS * sizeof(float)>>>(E, pos, dw, db, his, mask);
    k_trans<<<CC, 256>>>();
    k_tail<<<BB, 512>>>(E, W1, pos, mask, midb, out, (long)out_size);
}

// round 14
// speedup vs baseline: 1.2067x; 1.2067x over previous
#include <cuda_runtime.h>
#include <math.h>

#define NMID 500000
#define DD 64
#define KI 4
#define CC 512
#define SS 256
#define BB 512
#define NEGV (-4294967295.0f)
#define FMIN2 (-3.402823466e38f)

#define IST 68
#define QST 264
#define SST 260
#define SM_FLOATS 51328

typedef unsigned long long u64;

__device__ __forceinline__ u64 splat2(float x) {
    u64 r; asm("mov.b64 %0, {%1,%1};" : "=l"(r) : "f"(x)); return r;
}
__device__ __forceinline__ void ffma2(u64& acc, u64 a, u64 b) {
    asm("fma.rn.f32x2 %0, %1, %2, %0;" : "+l"(acc) : "l"(a), "l"(b));
}
__device__ __forceinline__ float2 unpack2(u64 v) {
    float2 f; asm("mov.b64 {%0,%1}, %2;" : "=f"(f.x), "=f"(f.y) : "l"(v)); return f;
}
__device__ __forceinline__ float tanh_fast(float x) {
    float t = __expf(2.f * x);
    return 1.f - __fdividef(2.f, t + 1.f);
}

__device__ float g_wmean[KI*DD];
__device__ float g_posSum[DD];
__device__ float g_cand0[CC*DD];
__device__ float g_cand[CC*DD];
__device__ float g_candW4[CC*DD];
__device__ float g_transT[(size_t)CC*CC];
__device__ float g_seq[(size_t)BB*SS*DD];
__device__ float g_mean[BB*DD];
__device__ float g_mh[BB*DD];
__device__ float g_L1[(size_t)BB*CC];
__device__ float g_L2[(size_t)BB*CC];

// ---------------- K0 ----------------
__global__ void k_pre(const float* __restrict__ pos) {
    int t = threadIdx.x;
    if (t < KI*DD) g_wmean[t] = 0.f;
    if (t < DD) {
        float s = 0.f;
        for (int i = 0; i < SS; i++) s += pos[i*DD + t];
        g_posSum[t] = s;
    }
}

// ---------------- K1 ----------------
__global__ void k_wmean(const float* __restrict__ E, const float* __restrict__ W2) {
    __shared__ float red[8*256];
    int t = threadIdx.x, l = t & 31, wi = t >> 5;
    int gw = (blockIdx.x*blockDim.x + t) >> 5;
    int TW = (gridDim.x*blockDim.x) >> 5;
    float2 w2[KI];
#pragma unroll
    for (int k = 0; k < KI; k++) {
        w2[k].x = W2[k*DD + 2*l];
        w2[k].y = W2[k*DD + 2*l + 1];
    }
    float2 acc[KI];
#pragma unroll
    for (int k = 0; k < KI; k++) acc[k] = make_float2(0.f, 0.f);
    const float2* E2 = (const float2*)E;
    for (long n = gw; n < NMID; n += TW) {
        float2 e = E2[n*32 + l];
#pragma unroll
        for (int k = 0; k < KI; k++) {
            float p = fmaf(e.x, w2[k].x, e.y*w2[k].y);
#pragma unroll
            for (int o = 16; o; o >>= 1) p += __shfl_xor_sync(~0u, p, o);
            acc[k].x = fmaf(p, e.x, acc[k].x);
            acc[k].y = fmaf(p, e.y, acc[k].y);
        }
    }
#pragma unroll
    for (int k = 0; k < KI; k++) {
        red[wi*256 + k*64 + 2*l]     = acc[k].x;
        red[wi*256 + k*64 + 2*l + 1] = acc[k].y;
    }
    __syncthreads();
    if (t < 256) {
        float s = 0.f;
#pragma unroll
        for (int w = 0; w < 8; w++) s += red[w*256 + t];
        atomicAdd(&g_wmean[t], s);
    }
}

// ---------------- K2 ----------------
__global__ void k_cand(const float* __restrict__ W3, const float* __restrict__ W1,
                       const float* __restrict__ W4) {
    __shared__ float row[DD];
    int d = threadIdx.x, c = blockIdx.x;
    float v = 0.f;
#pragma unroll
    for (int k = 0; k < KI; k++) v = fmaf(W3[k*CC + c], g_wmean[k*DD + d], v);
    row[d] = v;
    g_cand0[c*DD + d] = v;
    __syncthreads();
    float a = 0.f, bv = 0.f;
#pragma unroll 8
    for (int e = 0; e < DD; e++) {
        float r = row[e];
        a  = fmaf(r, W1[e*DD + d], a);
        bv = fmaf(r, W4[e*DD + d], bv);
    }
    g_cand[c*DD + d]   = tanhf(a);
    g_candW4[c*DD + d] = bv;
}

// ---------------- K4a: heavy per-batch part (unchanged) ----------------
__global__ void __launch_bounds__(1024,1) k_heavy(
    const float* __restrict__ E, const float* __restrict__ pos,
    const float* __restrict__ dw, const float* __restrict__ db,
    const int* __restrict__ his, const int* __restrict__ mask)
{
    extern __shared__ float sm[];
    float* itemsS = sm;
    float* qT     = sm + 17408;
    float* sc     = sm + 34304;
    float* maskS  = sm + 50944;
    float* colS   = sm + 51200;
    __shared__ float sDen;

    int b = blockIdx.x, t = threadIdx.x, w = t >> 5, l = t & 31;

    if (t < SS) maskS[t] = (float)mask[b*SS + t];
    if (t < 64) colS[t] = 0.f;
    {
        float* dwS = sc; float* biasS = sc + 4096;
        for (int i = t; i < 4096; i += 1024) dwS[i] = dw[i];
        if (t < 64) biasS[t] = db[t];
    }
    {
        const float4* E4 = (const float4*)E;
        float4* it4 = (float4*)itemsS;
        const int* hr = his + b*SS;
        for (int f = t; f < SS*16; f += 1024) {
            int s = f >> 4, c = f & 15;
            it4[s*17 + c] = E4[(size_t)hr[s]*16 + c];
        }
    }
    __syncthreads();
    if (w == 0) {
        float s = 0.f;
        for (int i = l; i < SS; i += 32) s += maskS[i];
#pragma unroll
        for (int o = 16; o; o >>= 1) s += __shfl_xor_sync(~0u, s, o);
        if (l == 0) sDen = 1.f / (s + 1e-9f);
    }

    {
        float* dwS = sc; float* biasS = sc + 4096;
        int s = t >> 2, q4 = t & 3;
        int d0 = 16*q4;
        u64 acc[8];
#pragma unroll
        for (int i = 0; i < 8; i++) acc[i] = 0ull;
#pragma unroll 4
        for (int e = 0; e < 64; e++) {
            float xe = itemsS[s*IST + e] + pos[s*DD + e];
            u64 xs = splat2(xe);
            const ulonglong2* wp = (const ulonglong2*)&dwS[e*64 + d0];
#pragma unroll
            for (int q = 0; q < 4; q++) {
                ulonglong2 wv = wp[q];
                ffma2(acc[2*q],   xs, wv.x);
                ffma2(acc[2*q+1], xs, wv.y);
            }
        }
#pragma unroll
        for (int i = 0; i < 8; i++) {
            float2 p = unpack2(acc[i]);
            int d = d0 + 2*i;
            qT[d*QST + s]     = tanhf(p.x + biasS[d]);
            qT[(d+1)*QST + s] = tanhf(p.y + biasS[d+1]);
        }
    }
    __syncthreads();

    float rs0 = 0.f, rs1 = 0.f;
    for (int g = 0; g < 4; g++) {
        int s0 = g*64;
        {
            int ty = t >> 7;
            int tx = t & 127;
            u64 acc[4][2];
#pragma unroll
            for (int i = 0; i < 4; i++) { acc[i][0] = 0ull; acc[i][1] = 0ull; }
#pragma unroll 4
            for (int e = 0; e < 64; e++) {
                const float* qe = &qT[e*QST];
                ulonglong2 a01 = *(const ulonglong2*)&qe[s0 + 8*ty];
                ulonglong2 a23 = *(const ulonglong2*)&qe[s0 + 8*ty + 4];
                float2 bf = *(const float2*)&qe[2*tx];
                u64 b0 = splat2(bf.x), b1 = splat2(bf.y);
                ffma2(acc[0][0], a01.x, b0); ffma2(acc[0][1], a01.x, b1);
                ffma2(acc[1][0], a01.y, b0); ffma2(acc[1][1], a01.y, b1);
                ffma2(acc[2][0], a23.x, b0); ffma2(acc[2][1], a23.x, b1);
                ffma2(acc[3][0], a23.y, b0); ffma2(acc[3][1], a23.y, b1);
            }
#pragma unroll
            for (int rp = 0; rp < 4; rp++) {
                float2 c0 = unpack2(acc[rp][0]);
                float2 c1 = unpack2(acc[rp][1]);
                *(float2*)&sc[(8*ty + 2*rp)*SST + 2*tx]     = make_float2(c0.x, c1.x);
                *(float2*)&sc[(8*ty + 2*rp + 1)*SST + 2*tx] = make_float2(c0.y, c1.y);
            }
        }
        __syncthreads();
        for (int rr = w; rr < 64; rr += 32) {
            int s = s0 + rr;
            if (maskS[s] == 0.f) {
                for (int c = l; c < 256; c += 32) sc[rr*SST + c] = 0.f;
            } else {
                float v[8]; float mx = FMIN2;
#pragma unroll
                for (int c = 0; c < 8; c++) {
                    float rawv = sc[rr*SST + l + 32*c] * 0.125f;
                    if (maskS[l + 32*c] == 0.f) rawv = NEGV;
                    v[c] = rawv; mx = fmaxf(mx, rawv);
                }
#pragma unroll
                for (int o = 16; o; o >>= 1) mx = fmaxf(mx, __shfl_xor_sync(~0u, mx, o));
                float sum = 0.f;
#pragma unroll
                for (int c = 0; c < 8; c++) { v[c] = expf(v[c] - mx); sum += v[c]; }
#pragma unroll
                for (int o = 16; o; o >>= 1) sum += __shfl_xor_sync(~0u, sum, o);
                float inv = 1.f / sum;
#pragma unroll
                for (int c = 0; c < 8; c++) sc[rr*SST + l + 32*c] = v[c]*inv;
            }
        }
        __syncthreads();
        {
            int ry = t >> 5;
            int rx = t & 31;
            u64 acc0 = 0ull, acc1 = 0ull;
            const float* r0p = &sc[(2*ry)*SST];
            const float* r1p = &sc[(2*ry + 1)*SST];
#pragma unroll 4
            for (int k = 0; k < 256; k += 2) {
                float2 af0 = *(const float2*)&r0p[k];
                float2 af1 = *(const float2*)&r1p[k];
                u64 bk  = *(const u64*)&itemsS[k*IST + 2*rx];
                u64 bk1 = *(const u64*)&itemsS[(k+1)*IST + 2*rx];
                ffma2(acc0, splat2(af0.x), bk);
                ffma2(acc1, splat2(af1.x), bk);
                ffma2(acc0, splat2(af0.y), bk1);
                ffma2(acc1, splat2(af1.y), bk1);
            }
            float2 u0 = unpack2(acc0), u1 = unpack2(acc1);
            float* so = &g_seq[((size_t)b*SS + s0 + 2*ry)*DD + 2*rx];
            *(float2*)so = u0;
            *(float2*)(so + DD) = u1;
            rs0 += u0.x + u1.x;
            rs1 += u0.y + u1.y;
        }
        __syncthreads();
    }
    {
        int rx = t & 31;
        atomicAdd(&colS[2*rx],   rs0);
        atomicAdd(&colS[2*rx+1], rs1);
    }
    __syncthreads();
    if (t < 64) g_mean[b*64 + t] = (colS[t] + g_posSum[t]) * sDen;
}

// ============ Tiled GEMM kernels (out[i][j] = sum_e A[i][e]*B[j][e]) ============
// 64x64 tile, 256 threads, 4x4 outputs/thread, f32x2 packed over j-pairs.
// Per-output accumulation is e-ascending single-fmaf -> bitwise == GEMV chains.

// trans scores: A=candW4 (i), B=cand0 (j); store to g_transT[j*CC + i]
__global__ void __launch_bounds__(256) k_transmm() {
    __shared__ float AS[64*68];
    __shared__ float BT[64*66];
    int t = threadIdx.x;
    int i0 = blockIdx.x*64, j0 = blockIdx.y*64;
    {
        const float4* Ag = (const float4*)g_candW4;
        float4* AS4 = (float4*)AS;
        for (int idx = t; idx < 1024; idx += 256) {
            int r = idx >> 4, f = idx & 15;
            AS4[r*17 + f] = Ag[(size_t)(i0 + r)*16 + f];
        }
        for (int idx = t; idx < 4096; idx += 256) {
            int e = idx & 63, bb = idx >> 6;
            BT[e*66 + bb] = g_cand0[(size_t)(j0 + bb)*64 + e];
        }
    }
    __syncthreads();
    int iq = t >> 4, jq = t & 15;
    u64 acc[4][2];
#pragma unroll
    for (int i = 0; i < 4; i++) { acc[i][0] = 0ull; acc[i][1] = 0ull; }
#pragma unroll 4
    for (int e4 = 0; e4 < 16; e4++) {
        float avf[16];
#pragma unroll
        for (int i = 0; i < 4; i++) {
            float4 v = *(const float4*)&AS[(iq*4 + i)*68 + e4*4];
            avf[i*4+0]=v.x; avf[i*4+1]=v.y; avf[i*4+2]=v.z; avf[i*4+3]=v.w;
        }
#pragma unroll
        for (int q = 0; q < 4; q++) {
            int e = 4*e4 + q;
            u64 m0 = *(const u64*)&BT[e*66 + jq*4];
            u64 m1 = *(const u64*)&BT[e*66 + jq*4 + 2];
#pragma unroll
            for (int i = 0; i < 4; i++) {
                u64 s = splat2(avf[i*4+q]);
                ffma2(acc[i][0], s, m0);
                ffma2(acc[i][1], s, m1);
            }
        }
    }
#pragma unroll
    for (int i = 0; i < 4; i++) {
        float2 u0 = unpack2(acc[i][0]);
        float2 u1 = unpack2(acc[i][1]);
        int ii = i0 + iq*4 + i;
        int jj = j0 + jq*4;
        g_transT[(size_t)(jj+0)*CC + ii] = u0.x;
        g_transT[(size_t)(jj+1)*CC + ii] = u0.y;
        g_transT[(size_t)(jj+2)*CC + ii] = u1.x;
        g_transT[(size_t)(jj+3)*CC + ii] = u1.y;
    }
}

// softmax over i within each row j of g_transT (identical reduction to old k_trans)
__global__ void __launch_bounds__(256) k_transsm() {
    __shared__ float red[8];
    __shared__ float bmax, bsum;
    int t = threadIdx.x, j = blockIdx.x, w = t >> 5, l = t & 31;
    float v0 = g_transT[(size_t)j*CC + t];
    float v1 = g_transT[(size_t)j*CC + t + 256];
    float m = fmaxf(v0, v1);
#pragma unroll
    for (int o = 16; o; o >>= 1) m = fmaxf(m, __shfl_xor_sync(~0u, m, o));
    if (l == 0) red[w] = m;
    __syncthreads();
    if (t == 0) { float mm = red[0]; for (int i = 1; i < 8; i++) mm = fmaxf(mm, red[i]); bmax = mm; }
    __syncthreads();
    float p0 = expf(v0 - bmax), p1 = expf(v1 - bmax);
    float s = p0 + p1;
#pragma unroll
    for (int o = 16; o; o >>= 1) s += __shfl_xor_sync(~0u, s, o);
    if (l == 0) red[w] = s;
    __syncthreads();
    if (t == 0) { float ss = 0.f; for (int i = 0; i < 8; i++) ss += red[i]; bsum = ss; }
    __syncthreads();
    float inv = 1.f / bsum;
    g_transT[(size_t)j*CC + t]       = p0 * inv;
    g_transT[(size_t)j*CC + t + 256] = p1 * inv;
}

// mh = tanh(mean @ W1): grid 64, 8 b per block
__global__ void __launch_bounds__(512) k_mh(const float* __restrict__ W1) {
    __shared__ float W1S[4096];
    __shared__ float meanS[512];
    int t = threadIdx.x;
    int b0 = blockIdx.x*8;
    for (int i = t; i < 4096; i += 512) W1S[i] = W1[i];
    meanS[t] = g_mean[b0*64 + t];
    __syncthreads();
    int bb = t >> 6, d = t & 63;
    float a = 0.f;
#pragma unroll 16
    for (int e = 0; e < 64; e++) a = fmaf(meanS[bb*64 + e], W1S[e*64 + d], a);
    g_mh[(size_t)(b0 + bb)*64 + d] = tanhf(a);
}

// L1[b][c] = cand[c] . mh[b] : A=g_cand (i=c), B=g_mh (j=b); store g_L1[b*CC + c]
__global__ void __launch_bounds__(256) k_logits1() {
    __shared__ float AS[64*68];
    __shared__ float BT[64*66];
    int t = threadIdx.x;
    int c0 = blockIdx.x*64, b0 = blockIdx.y*64;
    {
        const float4* Ag = (const float4*)g_cand;
        float4* AS4 = (float4*)AS;
        for (int idx = t; idx < 1024; idx += 256) {
            int r = idx >> 4, f = idx & 15;
            AS4[r*17 + f] = Ag[(size_t)(c0 + r)*16 + f];
        }
        for (int idx = t; idx < 4096; idx += 256) {
            int e = idx & 63, bb = idx >> 6;
            BT[e*66 + bb] = g_mh[(size_t)(b0 + bb)*64 + e];
        }
    }
    __syncthreads();
    int iq = t >> 4, jq = t & 15;
    u64 acc[4][2];
#pragma unroll
    for (int i = 0; i < 4; i++) { acc[i][0] = 0ull; acc[i][1] = 0ull; }
#pragma unroll 4
    for (int e4 = 0; e4 < 16; e4++) {
        float avf[16];
#pragma unroll
        for (int i = 0; i < 4; i++) {
            float4 v = *(const float4*)&AS[(iq*4 + i)*68 + e4*4];
            avf[i*4+0]=v.x; avf[i*4+1]=v.y; avf[i*4+2]=v.z; avf[i*4+3]=v.w;
        }
#pragma unroll
        for (int q = 0; q < 4; q++) {
            int e = 4*e4 + q;
            u64 m0 = *(const u64*)&BT[e*66 + jq*4];
            u64 m1 = *(const u64*)&BT[e*66 + jq*4 + 2];
#pragma unroll
            for (int i = 0; i < 4; i++) {
                u64 s = splat2(avf[i*4+q]);
                ffma2(acc[i][0], s, m0);
                ffma2(acc[i][1], s, m1);
            }
        }
    }
#pragma unroll
    for (int i = 0; i < 4; i++) {
        float2 u0 = unpack2(acc[i][0]);
        float2 u1 = unpack2(acc[i][1]);
        int cc = c0 + iq*4 + i;
        int bb = b0 + jq*4;
        g_L1[(size_t)(bb+0)*CC + cc] = u0.x;
        g_L1[(size_t)(bb+1)*CC + cc] = u0.y;
        g_L1[(size_t)(bb+2)*CC + cc] = u1.x;
        g_L1[(size_t)(bb+3)*CC + cc] = u1.y;
    }
}

// L2[b][t] = sum_i transT[t][i] * L1[b][i] : A=g_transT rows t, B=g_L1 rows b, k=512 in 8 chunks
__global__ void __launch_bounds__(256) k_logits2() {
    __shared__ float AS[64*68];
    __shared__ float BT[64*66];
    int t = threadIdx.x;
    int t0 = blockIdx.x*64, b0 = blockIdx.y*64;
    int iq = t >> 4, jq = t & 15;
    u64 acc[4][2];
#pragma unroll
    for (int i = 0; i < 4; i++) { acc[i][0] = 0ull; acc[i][1] = 0ull; }
    for (int ch = 0; ch < 8; ch++) {
        __syncthreads();
        {
            const float4* Ag = (const float4*)g_transT;
            float4* AS4 = (float4*)AS;
            for (int idx = t; idx < 1024; idx += 256) {
                int r = idx >> 4, f = idx & 15;
                AS4[r*17 + f] = Ag[(size_t)(t0 + r)*128 + ch*16 + f];
            }
            for (int idx = t; idx < 4096; idx += 256) {
                int e = idx & 63, bb = idx >> 6;
                BT[e*66 + bb] = g_L1[(size_t)(b0 + bb)*CC + ch*64 + e];
            }
        }
        __syncthreads();
#pragma unroll 4
        for (int e4 = 0; e4 < 16; e4++) {
            float avf[16];
#pragma unroll
            for (int i = 0; i < 4; i++) {
                float4 v = *(const float4*)&AS[(iq*4 + i)*68 + e4*4];
                avf[i*4+0]=v.x; avf[i*4+1]=v.y; avf[i*4+2]=v.z; avf[i*4+3]=v.w;
            }
#pragma unroll
            for (int q = 0; q < 4; q++) {
                int e = 4*e4 + q;
                u64 m0 = *(const u64*)&BT[e*66 + jq*4];
                u64 m1 = *(const u64*)&BT[e*66 + jq*4 + 2];
#pragma unroll
                for (int i = 0; i < 4; i++) {
                    u64 s = splat2(avf[i*4+q]);
                    ffma2(acc[i][0], s, m0);
                    ffma2(acc[i][1], s, m1);
                }
            }
        }
    }
#pragma unroll
    for (int i = 0; i < 4; i++) {
        float2 u0 = unpack2(acc[i][0]);
        float2 u1 = unpack2(acc[i][1]);
        int tt = t0 + iq*4 + i;
        int bb = b0 + jq*4;
        g_L2[(size_t)(bb+0)*CC + tt] = u0.x;
        g_L2[(size_t)(bb+1)*CC + tt] = u0.y;
        g_L2[(size_t)(bb+2)*CC + tt] = u1.x;
        g_L2[(size_t)(bb+3)*CC + tt] = u1.y;
    }
}

// ---------------- K4b: per-batch tail (top4 + multi-interest + outputs) ----------------
__global__ void __launch_bounds__(512) k_tail2(
    const float* __restrict__ E, const float* __restrict__ W1,
    const float* __restrict__ pos, const int* __restrict__ mask,
    const int* __restrict__ midb, float* __restrict__ out, long out_size)
{
    __shared__ float W1S[4096];
    __shared__ float logitsS[512];
    __shared__ float wrS[4*260];
    __shared__ float aqS[256];
    __shared__ float uebS[256];
    __shared__ float maskS[256];
    __shared__ float itemS[64];
    __shared__ float rv[16]; __shared__ int riS[16];
    __shared__ int idxS[4];
    __shared__ float dotS[4]; __shared__ int ridxS;

    int b = blockIdx.x, t = threadIdx.x, w = t >> 5, l = t & 31;

    if (t < SS) maskS[t] = (float)mask[b*SS + t];
    if (t < 64) itemS[t] = E[(size_t)midb[b]*DD + t];
    for (int i = t; i < 4096; i += 512) W1S[i] = W1[i];
    logitsS[t] = g_L2[(size_t)b*CC + t];
    __syncthreads();

    for (int p = 0; p < 4; p++) {
        float bv = logitsS[t]; int bi = t;
#pragma unroll
        for (int o = 16; o; o >>= 1) {
            float ov = __shfl_xor_sync(~0u, bv, o);
            int   oi = __shfl_xor_sync(~0u, bi, o);
            if (ov > bv || (ov == bv && oi < bi)) { bv = ov; bi = oi; }
        }
        if (l == 0) { rv[w] = bv; riS[w] = bi; }
        __syncthreads();
        if (t == 0) {
            float B2 = rv[0]; int BI = riS[0];
            for (int i = 1; i < 16; i++)
                if (rv[i] > B2 || (rv[i] == B2 && riS[i] < BI)) { B2 = rv[i]; BI = riS[i]; }
            idxS[p] = BI; logitsS[BI] = FMIN2;
        }
        __syncthreads();
    }
    if (t < 256) { int k = t >> 6, d = t & 63; aqS[t] = g_cand[(size_t)idxS[k]*64 + d]; }
    __syncthreads();

    // D: multi-interest attention (fast math OK: feeds outputs 0/1 only)
    {
        int s = t >> 1, half = t & 1;
        int d0 = 32*half;
        u64 acc[16];
#pragma unroll
        for (int i = 0; i < 16; i++) acc[i] = 0ull;
        const float4* sr4 = (const float4*)&g_seq[((size_t)b*SS + s)*DD];
        const float4* pp4 = (const float4*)&pos[s*DD];
#pragma unroll 4
        for (int e4 = 0; e4 < 16; e4++) {
            float4 sv = sr4[e4], pv = pp4[e4];
            float xs4[4];
            xs4[0] = sv.x + pv.x; xs4[1] = sv.y + pv.y;
            xs4[2] = sv.z + pv.z; xs4[3] = sv.w + pv.w;
#pragma unroll
            for (int q = 0; q < 4; q++) {
                u64 xs = splat2(xs4[q]);
                const ulonglong2* wp = (const ulonglong2*)&W1S[(4*e4+q)*64 + d0];
#pragma unroll
                for (int r = 0; r < 8; r++) {
                    ulonglong2 wv = wp[r];
                    ffma2(acc[2*r],   xs, wv.x);
                    ffma2(acc[2*r+1], xs, wv.y);
                }
            }
        }
        float ihv[32];
#pragma unroll
        for (int i = 0; i < 16; i++) {
            float2 p = unpack2(acc[i]);
            ihv[2*i]   = tanh_fast(p.x);
            ihv[2*i+1] = tanh_fast(p.y);
        }
        float wv[4];
#pragma unroll
        for (int k = 0; k < 4; k++) {
            float a = 0.f;
            const float* aq = &aqS[k*64 + d0];
#pragma unroll
            for (int i = 0; i < 32; i++) a = fmaf(ihv[i], aq[i], a);
            a += __shfl_xor_sync(~0u, a, 1);
            wv[k] = a;
        }
        if (half == 0) {
            float m = maskS[s];
#pragma unroll
            for (int k = 0; k < 4; k++)
                wrS[k*260 + s] = (m == 0.f) ? NEGV : wv[k];
        }
    }
    __syncthreads();
    if (w < 4) {
        float v[8]; float mx = FMIN2;
#pragma unroll
        for (int c = 0; c < 8; c++) { v[c] = wrS[w*260 + l + 32*c]; mx = fmaxf(mx, v[c]); }
#pragma unroll
        for (int o = 16; o; o >>= 1) mx = fmaxf(mx, __shfl_xor_sync(~0u, mx, o));
        float sum = 0.f;
#pragma unroll
        for (int c = 0; c < 8; c++) { v[c] = __expf(v[c] - mx); sum += v[c]; }
#pragma unroll
        for (int o = 16; o; o >>= 1) sum += __shfl_xor_sync(~0u, sum, o);
        float inv = 1.f / sum;
#pragma unroll
        for (int c = 0; c < 8; c++) wrS[w*260 + l + 32*c] = v[c]*inv;
    }
    __syncthreads();
    if (t < 256) {
        int k = t >> 6, d = t & 63;
        const float* wp = &wrS[k*260];
        const float* sp = &g_seq[(size_t)b*SS*DD + d];
        float a = 0.f;
#pragma unroll 8
        for (int s = 0; s < 256; s++) a = fmaf(wp[s], sp[(size_t)s*64], a);
        uebS[t] = a;
        long off = 32768 + (long)b*256 + t;
        if (off < out_size) out[off] = a;
    }
    __syncthreads();
    if (w < 4) {
        float p = uebS[w*64 + l]*itemS[l] + uebS[w*64 + l + 32]*itemS[l + 32];
#pragma unroll
        for (int o = 16; o; o >>= 1) p += __shfl_xor_sync(~0u, p, o);
        if (l == 0) dotS[w] = p;
    }
    __syncthreads();
    if (t == 0) {
        float bv2 = dotS[0]; int bi2 = 0;
        for (int k = 1; k < 4; k++) if (dotS[k] > bv2) { bv2 = dotS[k]; bi2 = k; }
        ridxS = bi2;
    }
    __syncthreads();
    if (t < 64) {
        long off = (long)b*64 + t;
        if (off < out_size) out[off] = uebS[ridxS*64 + t];
    }
    if (t < 4) {
        long off = 163840 + (long)b*4 + t;
        if (off < out_size) out[off] = (float)idxS[t];
    }
}

extern "C" void kernel_launch(void* const* d_in, const int* in_sizes, int n_in,
                              void* d_out, int out_size) {
    const float* E    = (const float*)d_in[0];
    const float* W1   = (const float*)d_in[1];
    const float* W2   = (const float*)d_in[2];
    const float* W3   = (const float*)d_in[3];
    const float* W4   = (const float*)d_in[4];
    const float* pos  = (const float*)d_in[5];
    const float* dw   = (const float*)d_in[6];
    const float* db   = (const float*)d_in[7];
    const int*   his  = (const int*)d_in[8];
    const int*   mask = (const int*)d_in[9];
    const int*   midb = (const int*)d_in[10];
    float* out = (float*)d_out;

    cudaFuncSetAttribute(k_heavy, cudaFuncAttributeMaxDynamicSharedMemorySize,
                         SM_FLOATS * (int)sizeof(float));

    k_pre<<<1, 256>>>(pos);
    k_wmean<<<1184, 256>>>(E, W2);
    k_cand<<<CC, DD>>>(W3, W1, W4);
    k_heavy<<<BB, 1024, SM_FLOATS * sizeof(float)>>>(E, pos, dw, db, his, mask);
    k_transmm<<<dim3(8,8), 256>>>();
    k_transsm<<<CC, 256>>>();
    k_mh<<<64, 512>>>(W1);
    k_logits1<<<dim3(8,8), 256>>>();
    k_logits2<<<dim3(8,8), 256>>>();
    k_tail2<<<BB, 512>>>(E, W1, pos, mask, midb, out, (long)out_size);
}